// round 8
// baseline (speedup 1.0000x reference)
#include <cuda_runtime.h>
#include <cuda_bf16.h>
#include <math_constants.h>

// Problem constants
#define B_   32
#define NC_  4
#define HW_  262144                       // 512*512
#define NTOT 33554432.0                   // 32*4*512*512
#define BPI  64                           // blocks per image
#define TPB  256
#define G_   4                            // float4-groups per thread -> 16 px/thread
#define NBLK (B_ * BPI)                   // 2048

// Global accumulators (zero at module load; finalize kernel re-zeros each run)
__device__ double g_bce;
__device__ int g_tp[B_ * NC_];
__device__ int g_pc[B_ * NC_];
__device__ int g_tc[B_ * NC_];

__global__ __launch_bounds__(TPB) void seg_main_kernel(
    const float* __restrict__ pred, const float* __restrict__ tgt)
{
    const int b   = blockIdx.x >> 6;          // / BPI
    const int blk = blockIdx.x & (BPI - 1);
    const float* __restrict__ pb_ = pred + (long long)b * NC_ * HW_;
    const float* __restrict__ tb_ = tgt  + (long long)b * NC_ * HW_;

    float bce = 0.f;
    unsigned pcp = 0u, tcp = 0u, tpp = 0u;   // 8-bit packed per-class counters

#pragma unroll 1
    for (int g = 0; g < G_; ++g) {
        const int pix = blk * (TPB * G_ * 4) + g * (TPB * 4) + threadIdx.x * 4;

        // running argmax state for the 4 pixels of this float4 group
        float bp0 = -CUDART_INF_F, bp1 = -CUDART_INF_F, bp2 = -CUDART_INF_F, bp3 = -CUDART_INF_F;
        float bt0 = -CUDART_INF_F, bt1 = -CUDART_INF_F, bt2 = -CUDART_INF_F, bt3 = -CUDART_INF_F;
        int ap0 = 0, ap1 = 0, ap2 = 0, ap3 = 0;
        int at0 = 0, at1 = 0, at2 = 0, at3 = 0;

#pragma unroll
        for (int c = 0; c < NC_; ++c) {
            const float4 p = __ldcs(reinterpret_cast<const float4*>(pb_ + c * HW_ + pix));
            const float4 t = __ldcs(reinterpret_cast<const float4*>(tb_ + c * HW_ + pix));

            // BCE terms consumed immediately (short live range)
            bce += fmaxf(p.x, 0.f) - p.x * t.x + __logf(1.f + __expf(-fabsf(p.x)));
            bce += fmaxf(p.y, 0.f) - p.y * t.y + __logf(1.f + __expf(-fabsf(p.y)));
            bce += fmaxf(p.z, 0.f) - p.z * t.z + __logf(1.f + __expf(-fabsf(p.z)));
            bce += fmaxf(p.w, 0.f) - p.w * t.w + __logf(1.f + __expf(-fabsf(p.w)));

            // running argmax, first-max ties (strict > for later channels)
            if (p.x > bp0) { bp0 = p.x; ap0 = c; }
            if (p.y > bp1) { bp1 = p.y; ap1 = c; }
            if (p.z > bp2) { bp2 = p.z; ap2 = c; }
            if (p.w > bp3) { bp3 = p.w; ap3 = c; }
            if (t.x > bt0) { bt0 = t.x; at0 = c; }
            if (t.y > bt1) { bt1 = t.y; at1 = c; }
            if (t.z > bt2) { bt2 = t.z; at2 = c; }
            if (t.w > bt3) { bt3 = t.w; at3 = c; }
        }

        // confusion counters: four 8-bit fields per u32 (max 16/field/thread)
        unsigned pm0 = 1u << (ap0 << 3), pm1 = 1u << (ap1 << 3);
        unsigned pm2 = 1u << (ap2 << 3), pm3 = 1u << (ap3 << 3);
        pcp += pm0 + pm1 + pm2 + pm3;
        tcp += (1u << (at0 << 3)) + (1u << (at1 << 3)) +
               (1u << (at2 << 3)) + (1u << (at3 << 3));
        tpp += ((ap0 == at0) ? pm0 : 0u) + ((ap1 == at1) ? pm1 : 0u) +
               ((ap2 == at2) ? pm2 : 0u) + ((ap3 == at3) ? pm3 : 0u);
    }

    // expand 8-bit fields -> 16-bit fields in two u32 halves (one PRMT each)
    unsigned pc_lo = __byte_perm(pcp, 0u, 0x4140);
    unsigned pc_hi = __byte_perm(pcp, 0u, 0x4342);
    unsigned tc_lo = __byte_perm(tcp, 0u, 0x4140);
    unsigned tc_hi = __byte_perm(tcp, 0u, 0x4342);
    unsigned tp_lo = __byte_perm(tpp, 0u, 0x4140);
    unsigned tp_hi = __byte_perm(tpp, 0u, 0x4342);

    // warp reduction (16-bit fields: max 16/thread * 32 lanes = 512, no overflow)
#pragma unroll
    for (int o = 16; o > 0; o >>= 1)
        bce += __shfl_down_sync(0xFFFFFFFFu, bce, o);

    pc_lo = __reduce_add_sync(0xFFFFFFFFu, pc_lo);
    pc_hi = __reduce_add_sync(0xFFFFFFFFu, pc_hi);
    tc_lo = __reduce_add_sync(0xFFFFFFFFu, tc_lo);
    tc_hi = __reduce_add_sync(0xFFFFFFFFu, tc_hi);
    tp_lo = __reduce_add_sync(0xFFFFFFFFu, tp_lo);
    tp_hi = __reduce_add_sync(0xFFFFFFFFu, tp_hi);

    // block combine (block max 4096/field < 65536)
    __shared__ double s_bce;
    __shared__ unsigned s_cnt[6];   // pc_lo, pc_hi, tc_lo, tc_hi, tp_lo, tp_hi
    if (threadIdx.x == 0) s_bce = 0.0;
    if (threadIdx.x < 6) s_cnt[threadIdx.x] = 0u;
    __syncthreads();

    if ((threadIdx.x & 31) == 0) {
        atomicAdd(&s_bce, (double)bce);
        atomicAdd(&s_cnt[0], pc_lo);
        atomicAdd(&s_cnt[1], pc_hi);
        atomicAdd(&s_cnt[2], tc_lo);
        atomicAdd(&s_cnt[3], tc_hi);
        atomicAdd(&s_cnt[4], tp_lo);
        atomicAdd(&s_cnt[5], tp_hi);
    }
    __syncthreads();

    if (threadIdx.x < NC_) {
        const int c = threadIdx.x;
        const int sh = (c & 1) * 16;
        const int w  = c >> 1;                  // 0 -> lo word (cls 0,1), 1 -> hi (cls 2,3)
        atomicAdd(&g_pc[b * NC_ + c], (int)((s_cnt[0 + w] >> sh) & 0xFFFFu));
        atomicAdd(&g_tc[b * NC_ + c], (int)((s_cnt[2 + w] >> sh) & 0xFFFFu));
        atomicAdd(&g_tp[b * NC_ + c], (int)((s_cnt[4 + w] >> sh) & 0xFFFFu));
    }
    if (threadIdx.x == 0)
        atomicAdd(&g_bce, s_bce);
}

__global__ void seg_final_kernel(float* __restrict__ out) {
    const int b = threadIdx.x;   // 32 threads, one per batch sample
    float iou_sum = 0.f;
    int present = 0;
#pragma unroll
    for (int c = 0; c < NC_; ++c) {
        const int i = b * NC_ + c;
        int tpv = g_tp[i], pcv = g_pc[i], tcv = g_tc[i];
        int denom = pcv + tcv - tpv;
        if (denom > 0) iou_sum += (float)tpv / (float)denom;
        present += (tcv > 0);
        // reset for the next graph replay
        g_tp[i] = 0; g_pc[i] = 0; g_tc[i] = 0;
    }
    float val = iou_sum / (float)present;   // present >= 1 (targets cover all pixels)

#pragma unroll
    for (int o = 16; o > 0; o >>= 1)
        val += __shfl_down_sync(0xFFFFFFFFu, val, o);

    if (b == 0) {
        out[0] = (float)(g_bce / NTOT);     // lseg
        out[1] = 1.0f - val / (float)B_;    // liou
        g_bce = 0.0;                        // reset for next replay
    }
}

extern "C" void kernel_launch(void* const* d_in, const int* in_sizes, int n_in,
                              void* d_out, int out_size) {
    const float* pred = (const float*)d_in[0];
    const float* tgt  = (const float*)d_in[1];
    float* out = (float*)d_out;

    seg_main_kernel<<<NBLK, TPB>>>(pred, tgt);
    seg_final_kernel<<<1, 32>>>(out);
}

// round 9
// speedup vs baseline: 1.0143x; 1.0143x over previous
#include <cuda_runtime.h>
#include <cuda_bf16.h>

// Problem constants
#define B_   32
#define NC_  4
#define HW_  262144                       // 512*512
#define NTOT 33554432.0                   // 32*4*512*512
#define BPI  64                           // blocks per image
#define TPB  256
#define G_   4                            // float4-groups per thread -> 16 px/thread
#define NBLK (B_ * BPI)                   // 2048

// Global accumulators (zero at module load; finalize kernel re-zeros each run)
__device__ double g_bce;
__device__ int g_tp[B_ * NC_];
__device__ int g_pc[B_ * NC_];
__device__ int g_tc[B_ * NC_];

__device__ __forceinline__ void px(
    float p0, float p1, float p2, float p3,
    float t0, float t1, float t2, float t3,
    float& bce,
    unsigned long long& pcp, unsigned long long& tcp, unsigned long long& tpp)
{
    // argmax, first-max tie semantics (strict > for later indices)
    float bp = p0; int ap = 0;
    if (p1 > bp) { bp = p1; ap = 1; }
    if (p2 > bp) { bp = p2; ap = 2; }
    if (p3 > bp) { bp = p3; ap = 3; }
    float bt = t0; int at = 0;
    if (t1 > bt) { bt = t1; at = 1; }
    if (t2 > bt) { bt = t2; at = 2; }
    if (t3 > bt) { bt = t3; at = 3; }

    // stable BCE-with-logits: max(x,0) - x*t + log(1 + exp(-|x|))
    // log arg in (1,2] -> MUFU.LG2 path has plenty of accuracy for a 1e-3 mean
    bce += fmaxf(p0, 0.f) - p0 * t0 + __logf(1.f + __expf(-fabsf(p0)));
    bce += fmaxf(p1, 0.f) - p1 * t1 + __logf(1.f + __expf(-fabsf(p1)));
    bce += fmaxf(p2, 0.f) - p2 * t2 + __logf(1.f + __expf(-fabsf(p2)));
    bce += fmaxf(p3, 0.f) - p3 * t3 + __logf(1.f + __expf(-fabsf(p3)));

    // packed confusion counters: four 16-bit fields per u64
    unsigned long long pb = 1ull << (ap << 4);
    pcp += pb;
    tcp += 1ull << (at << 4);
    tpp += (ap == at) ? pb : 0ull;
}

__global__ __launch_bounds__(TPB) void seg_main_kernel(
    const float* __restrict__ pred, const float* __restrict__ tgt)
{
    const int b   = blockIdx.x >> 6;          // / BPI
    const int blk = blockIdx.x & (BPI - 1);
    const long long base = (long long)b * NC_ * HW_;

    float bce = 0.f;
    unsigned long long pcp = 0ull, tcp = 0ull, tpp = 0ull;

#pragma unroll 1
    for (int g = 0; g < G_; ++g) {
        const int pix = blk * (TPB * G_ * 4) + g * (TPB * 4) + threadIdx.x * 4;

        float4 p4[NC_], t4[NC_];
#pragma unroll
        for (int c = 0; c < NC_; ++c) {
            p4[c] = __ldcs(reinterpret_cast<const float4*>(pred + base + (long long)c * HW_ + pix));
            t4[c] = __ldcs(reinterpret_cast<const float4*>(tgt  + base + (long long)c * HW_ + pix));
        }

        px(p4[0].x, p4[1].x, p4[2].x, p4[3].x,
           t4[0].x, t4[1].x, t4[2].x, t4[3].x, bce, pcp, tcp, tpp);
        px(p4[0].y, p4[1].y, p4[2].y, p4[3].y,
           t4[0].y, t4[1].y, t4[2].y, t4[3].y, bce, pcp, tcp, tpp);
        px(p4[0].z, p4[1].z, p4[2].z, p4[3].z,
           t4[0].z, t4[1].z, t4[2].z, t4[3].z, bce, pcp, tcp, tpp);
        px(p4[0].w, p4[1].w, p4[2].w, p4[3].w,
           t4[0].w, t4[1].w, t4[2].w, t4[3].w, bce, pcp, tcp, tpp);
    }

    // warp reduction (16-bit fields: max 16/thread * 32 lanes = 512, no overflow)
#pragma unroll
    for (int o = 16; o > 0; o >>= 1)
        bce += __shfl_down_sync(0xFFFFFFFFu, bce, o);

    unsigned pc_lo = __reduce_add_sync(0xFFFFFFFFu, (unsigned)pcp);
    unsigned pc_hi = __reduce_add_sync(0xFFFFFFFFu, (unsigned)(pcp >> 32));
    unsigned tc_lo = __reduce_add_sync(0xFFFFFFFFu, (unsigned)tcp);
    unsigned tc_hi = __reduce_add_sync(0xFFFFFFFFu, (unsigned)(tcp >> 32));
    unsigned tp_lo = __reduce_add_sync(0xFFFFFFFFu, (unsigned)tpp);
    unsigned tp_hi = __reduce_add_sync(0xFFFFFFFFu, (unsigned)(tpp >> 32));

    // block combine (block max 4096/field < 65536)
    __shared__ double s_bce;
    __shared__ unsigned s_cnt[6];   // pc_lo, pc_hi, tc_lo, tc_hi, tp_lo, tp_hi
    if (threadIdx.x == 0) s_bce = 0.0;
    if (threadIdx.x < 6) s_cnt[threadIdx.x] = 0u;
    __syncthreads();

    if ((threadIdx.x & 31) == 0) {
        atomicAdd(&s_bce, (double)bce);
        atomicAdd(&s_cnt[0], pc_lo);
        atomicAdd(&s_cnt[1], pc_hi);
        atomicAdd(&s_cnt[2], tc_lo);
        atomicAdd(&s_cnt[3], tc_hi);
        atomicAdd(&s_cnt[4], tp_lo);
        atomicAdd(&s_cnt[5], tp_hi);
    }
    __syncthreads();

    if (threadIdx.x < NC_) {
        const int c = threadIdx.x;
        const int sh = (c & 1) * 16;
        const int w  = c >> 1;                  // 0 -> lo word, 1 -> hi word
        atomicAdd(&g_pc[b * NC_ + c], (int)((s_cnt[0 + w] >> sh) & 0xFFFFu));
        atomicAdd(&g_tc[b * NC_ + c], (int)((s_cnt[2 + w] >> sh) & 0xFFFFu));
        atomicAdd(&g_tp[b * NC_ + c], (int)((s_cnt[4 + w] >> sh) & 0xFFFFu));
    }
    if (threadIdx.x == 0)
        atomicAdd(&g_bce, s_bce);
}

__global__ void seg_final_kernel(float* __restrict__ out) {
    // PDL: this grid launches early (overlapping the primary's execution);
    // the wait releases when ALL primary blocks complete (implicit trigger --
    // the primary never calls launch_dependents), with full memory visibility.
    asm volatile("griddepcontrol.wait;" ::: "memory");

    const int b = threadIdx.x;   // 32 threads, one per batch sample
    float iou_sum = 0.f;
    int present = 0;
#pragma unroll
    for (int c = 0; c < NC_; ++c) {
        const int i = b * NC_ + c;
        int tpv = g_tp[i], pcv = g_pc[i], tcv = g_tc[i];
        int denom = pcv + tcv - tpv;
        if (denom > 0) iou_sum += (float)tpv / (float)denom;
        present += (tcv > 0);
        // reset for the next graph replay
        g_tp[i] = 0; g_pc[i] = 0; g_tc[i] = 0;
    }
    float val = iou_sum / (float)present;   // present >= 1 (targets cover all pixels)

#pragma unroll
    for (int o = 16; o > 0; o >>= 1)
        val += __shfl_down_sync(0xFFFFFFFFu, val, o);

    if (b == 0) {
        out[0] = (float)(g_bce / NTOT);     // lseg
        out[1] = 1.0f - val / (float)B_;    // liou
        g_bce = 0.0;                        // reset for next replay
    }
}

extern "C" void kernel_launch(void* const* d_in, const int* in_sizes, int n_in,
                              void* d_out, int out_size) {
    const float* pred = (const float*)d_in[0];
    const float* tgt  = (const float*)d_in[1];
    float* out = (float*)d_out;

    seg_main_kernel<<<NBLK, TPB>>>(pred, tgt);

    // Finalize with programmatic stream serialization: launch overhead overlaps
    // the primary kernel; griddepcontrol.wait provides ordering + visibility.
    cudaLaunchAttribute attrs[1];
    attrs[0].id = cudaLaunchAttributeProgrammaticStreamSerialization;
    attrs[0].val.programmaticStreamSerializationAllowed = 1;

    cudaLaunchConfig_t cfg = {};
    cfg.gridDim = dim3(1, 1, 1);
    cfg.blockDim = dim3(32, 1, 1);
    cfg.dynamicSmemBytes = 0;
    cfg.stream = 0;
    cfg.attrs = attrs;
    cfg.numAttrs = 1;

    cudaLaunchKernelEx(&cfg, seg_final_kernel, out);
}

// round 10
// speedup vs baseline: 1.0591x; 1.0441x over previous
#include <cuda_runtime.h>
#include <cuda_bf16.h>

// Problem constants
#define B_   32
#define NC_  4
#define HW_  262144                       // 512*512
#define NTOT 33554432.0                   // 32*4*512*512
#define BPI  128                          // blocks per image
#define TPB  256
#define G_   2                            // float4-groups per thread -> 8 px/thread
#define NBLK (B_ * BPI)                   // 4096

// Global accumulators (zero at module load; finalize kernel re-zeros each run)
__device__ double g_bce;
__device__ int g_tp[B_ * NC_];
__device__ int g_pc[B_ * NC_];
__device__ int g_tc[B_ * NC_];

__device__ __forceinline__ void px(
    float p0, float p1, float p2, float p3,
    float t0, float t1, float t2, float t3,
    float& bce,
    unsigned long long& pcp, unsigned long long& tcp, unsigned long long& tpp)
{
    // argmax, first-max tie semantics (strict > for later indices)
    float bp = p0; int ap = 0;
    if (p1 > bp) { bp = p1; ap = 1; }
    if (p2 > bp) { bp = p2; ap = 2; }
    if (p3 > bp) { bp = p3; ap = 3; }
    float bt = t0; int at = 0;
    if (t1 > bt) { bt = t1; at = 1; }
    if (t2 > bt) { bt = t2; at = 2; }
    if (t3 > bt) { bt = t3; at = 3; }

    // stable BCE-with-logits: max(x,0) - x*t + log(1 + exp(-|x|))
    // log arg in (1,2] -> MUFU.LG2 path has plenty of accuracy for a 1e-3 mean
    bce += fmaxf(p0, 0.f) - p0 * t0 + __logf(1.f + __expf(-fabsf(p0)));
    bce += fmaxf(p1, 0.f) - p1 * t1 + __logf(1.f + __expf(-fabsf(p1)));
    bce += fmaxf(p2, 0.f) - p2 * t2 + __logf(1.f + __expf(-fabsf(p2)));
    bce += fmaxf(p3, 0.f) - p3 * t3 + __logf(1.f + __expf(-fabsf(p3)));

    // packed confusion counters: four 16-bit fields per u64
    unsigned long long pb = 1ull << (ap << 4);
    pcp += pb;
    tcp += 1ull << (at << 4);
    tpp += (ap == at) ? pb : 0ull;
}

__global__ __launch_bounds__(TPB) void seg_main_kernel(
    const float* __restrict__ pred, const float* __restrict__ tgt)
{
    const int b   = blockIdx.x >> 7;          // / BPI
    const int blk = blockIdx.x & (BPI - 1);
    const long long base = (long long)b * NC_ * HW_;

    float bce = 0.f;
    unsigned long long pcp = 0ull, tcp = 0ull, tpp = 0ull;

#pragma unroll 1
    for (int g = 0; g < G_; ++g) {
        const int pix = blk * (TPB * G_ * 4) + g * (TPB * 4) + threadIdx.x * 4;

        float4 p4[NC_], t4[NC_];
#pragma unroll
        for (int c = 0; c < NC_; ++c) {
            p4[c] = __ldcs(reinterpret_cast<const float4*>(pred + base + (long long)c * HW_ + pix));
            t4[c] = __ldcs(reinterpret_cast<const float4*>(tgt  + base + (long long)c * HW_ + pix));
        }

        px(p4[0].x, p4[1].x, p4[2].x, p4[3].x,
           t4[0].x, t4[1].x, t4[2].x, t4[3].x, bce, pcp, tcp, tpp);
        px(p4[0].y, p4[1].y, p4[2].y, p4[3].y,
           t4[0].y, t4[1].y, t4[2].y, t4[3].y, bce, pcp, tcp, tpp);
        px(p4[0].z, p4[1].z, p4[2].z, p4[3].z,
           t4[0].z, t4[1].z, t4[2].z, t4[3].z, bce, pcp, tcp, tpp);
        px(p4[0].w, p4[1].w, p4[2].w, p4[3].w,
           t4[0].w, t4[1].w, t4[2].w, t4[3].w, bce, pcp, tcp, tpp);
    }

    // warp reduction (16-bit fields: max 8/thread * 32 lanes = 256, no overflow)
#pragma unroll
    for (int o = 16; o > 0; o >>= 1)
        bce += __shfl_down_sync(0xFFFFFFFFu, bce, o);

    unsigned pc_lo = __reduce_add_sync(0xFFFFFFFFu, (unsigned)pcp);
    unsigned pc_hi = __reduce_add_sync(0xFFFFFFFFu, (unsigned)(pcp >> 32));
    unsigned tc_lo = __reduce_add_sync(0xFFFFFFFFu, (unsigned)tcp);
    unsigned tc_hi = __reduce_add_sync(0xFFFFFFFFu, (unsigned)(tcp >> 32));
    unsigned tp_lo = __reduce_add_sync(0xFFFFFFFFu, (unsigned)tpp);
    unsigned tp_hi = __reduce_add_sync(0xFFFFFFFFu, (unsigned)(tpp >> 32));

    // block combine (block max 2048/field < 65536)
    __shared__ double s_bce;
    __shared__ unsigned s_cnt[6];   // pc_lo, pc_hi, tc_lo, tc_hi, tp_lo, tp_hi
    if (threadIdx.x == 0) s_bce = 0.0;
    if (threadIdx.x < 6) s_cnt[threadIdx.x] = 0u;
    __syncthreads();

    if ((threadIdx.x & 31) == 0) {
        atomicAdd(&s_bce, (double)bce);
        atomicAdd(&s_cnt[0], pc_lo);
        atomicAdd(&s_cnt[1], pc_hi);
        atomicAdd(&s_cnt[2], tc_lo);
        atomicAdd(&s_cnt[3], tc_hi);
        atomicAdd(&s_cnt[4], tp_lo);
        atomicAdd(&s_cnt[5], tp_hi);
    }
    __syncthreads();

    if (threadIdx.x < NC_) {
        const int c = threadIdx.x;
        const int sh = (c & 1) * 16;
        const int w  = c >> 1;                  // 0 -> lo word, 1 -> hi word
        atomicAdd(&g_pc[b * NC_ + c], (int)((s_cnt[0 + w] >> sh) & 0xFFFFu));
        atomicAdd(&g_tc[b * NC_ + c], (int)((s_cnt[2 + w] >> sh) & 0xFFFFu));
        atomicAdd(&g_tp[b * NC_ + c], (int)((s_cnt[4 + w] >> sh) & 0xFFFFu));
    }
    if (threadIdx.x == 0)
        atomicAdd(&g_bce, s_bce);
}

__global__ void seg_final_kernel(float* __restrict__ out) {
    const int b = threadIdx.x;   // 32 threads, one per batch sample
    float iou_sum = 0.f;
    int present = 0;
#pragma unroll
    for (int c = 0; c < NC_; ++c) {
        const int i = b * NC_ + c;
        int tpv = g_tp[i], pcv = g_pc[i], tcv = g_tc[i];
        int denom = pcv + tcv - tpv;
        if (denom > 0) iou_sum += (float)tpv / (float)denom;
        present += (tcv > 0);
        // reset for the next graph replay
        g_tp[i] = 0; g_pc[i] = 0; g_tc[i] = 0;
    }
    float val = iou_sum / (float)present;   // present >= 1 (targets cover all pixels)

#pragma unroll
    for (int o = 16; o > 0; o >>= 1)
        val += __shfl_down_sync(0xFFFFFFFFu, val, o);

    if (b == 0) {
        out[0] = (float)(g_bce / NTOT);     // lseg
        out[1] = 1.0f - val / (float)B_;    // liou
        g_bce = 0.0;                        // reset for next replay
    }
}

extern "C" void kernel_launch(void* const* d_in, const int* in_sizes, int n_in,
                              void* d_out, int out_size) {
    const float* pred = (const float*)d_in[0];
    const float* tgt  = (const float*)d_in[1];
    float* out = (float*)d_out;

    seg_main_kernel<<<NBLK, TPB>>>(pred, tgt);
    seg_final_kernel<<<1, 32>>>(out);
}